// round 2
// baseline (speedup 1.0000x reference)
#include <cuda_runtime.h>
#include <cstdint>
#include <cstddef>

#define N_TOKENS   16384
#define IN_F       1024
#define OUT_F      1024
#define BH         32
#define BW         32
#define NB         256
#define N_RB       (OUT_F / BH)     // 32 row blocks
#define TOK_TILE   256
#define THREADS    256

// Per-row-block lists of sparse blocks (built by prep kernel, deterministic order).
__device__ int g_cnt[N_RB];
__device__ int g_blk[N_RB][NB];
__device__ int g_col[N_RB][NB];

__global__ void spmm_prep_kernel(const int* __restrict__ brow,
                                 const int* __restrict__ bcol) {
    int rb = threadIdx.x;
    if (rb >= N_RB) return;
    int c = 0;
    for (int b = 0; b < NB; ++b) {
        if (brow[b] == rb) {
            g_blk[rb][c] = b;
            g_col[rb][c] = bcol[b];
            ++c;
        }
    }
    g_cnt[rb] = c;
}

// CTA: TOK_TILE tokens x one 32-wide output row-block.
// Thread: 8 tokens (stride 32) x 4 output cols -> 16 packed f32x2 accumulators.
__global__ __launch_bounds__(THREADS)
void spmm_main_kernel(const float* __restrict__ x,
                      const float* __restrict__ w,
                      const float* __restrict__ bias,
                      float* __restrict__ out) {
    // xs4[kq][t] holds x[t][4*kq .. 4*kq+3] for the current col-block (as float4).
    // 257 padding: STS.128/LDS.128 conflict-free (257 % 8 == 1).
    __shared__ float4 xs4[8][TOK_TILE + 1];
    // ws[k][o]: W transposed so 4 consecutive output cols are contiguous (pairs for f32x2).
    // Row = 36 floats = 144 B: 16B-aligned rows, conflict-free LDS.128 across colq.
    __shared__ float ws[BW][BH + 4];

    const int rb   = blockIdx.y;
    const int tok0 = blockIdx.x * TOK_TILE;
    const int tid  = threadIdx.x;
    const int colq = tid & 7;    // 0..7 -> cols 4*colq .. 4*colq+3
    const int tg   = tid >> 3;   // 0..31 -> tokens tg + 32*j, j = 0..7

    unsigned long long acc[8][2];
#pragma unroll
    for (int j = 0; j < 8; ++j) { acc[j][0] = 0ULL; acc[j][1] = 0ULL; }

    const int cnt = g_cnt[rb];

    for (int i = 0; i < cnt; ++i) {
        const int b  = g_blk[rb][i];
        const int cb = g_col[rb][i];

        __syncthreads();   // previous iteration's reads done before refill

        // ---- fill W tile (transposed): w[b][o][k] -> ws[k][o] ----
        {
            const float4 wv = *(const float4*)(w + (size_t)b * (BH * BW) + tid * 4);
            const int o = tid >> 3;          // 0..31
            const int k = (tid & 7) * 4;     // 0,4,...,28
            ws[k + 0][o] = wv.x;
            ws[k + 1][o] = wv.y;
            ws[k + 2][o] = wv.z;
            ws[k + 3][o] = wv.w;
        }
        // ---- fill x tile: 256 tokens x 32 features (col block cb) ----
        {
            const float* xg = x + (size_t)tok0 * IN_F + cb * BW;
            const int kq = tid & 7;          // which float4 of the 32-wide row
            const int tb = tid >> 3;         // 0..31
#pragma unroll
            for (int r = 0; r < 8; ++r) {
                const int t = tb + 32 * r;   // 0..255
                xs4[kq][t] = *(const float4*)(xg + (size_t)t * IN_F + kq * 4);
            }
        }
        __syncthreads();

        // ---- compute: acc[j] += x[t][k] * W[o][k], packed over col pairs ----
#pragma unroll 8
        for (int k = 0; k < BW; ++k) {
            const ulonglong2 wp = *(const ulonglong2*)&ws[k][colq * 4];
            const int kq = k >> 2, kr = k & 3;
#pragma unroll
            for (int j = 0; j < 8; ++j) {
                const int t = tg + 32 * j;
                const float xv = ((const float*)&xs4[kq][t])[kr];
                unsigned long long x2;
                asm("mov.b64 %0, {%1, %1};" : "=l"(x2) : "f"(xv));
                asm("fma.rn.f32x2 %0, %1, %2, %0;"
                    : "+l"(acc[j][0]) : "l"(x2), "l"(wp.x));
                asm("fma.rn.f32x2 %0, %1, %2, %0;"
                    : "+l"(acc[j][1]) : "l"(x2), "l"(wp.y));
            }
        }
    }

    // ---- epilogue: unpack, add bias, coalesced STG.128 ----
    const float4 bv = *(const float4*)(bias + rb * BH + colq * 4);
#pragma unroll
    for (int j = 0; j < 8; ++j) {
        float lo0, hi0, lo1, hi1;
        asm("mov.b64 {%0, %1}, %2;" : "=f"(lo0), "=f"(hi0) : "l"(acc[j][0]));
        asm("mov.b64 {%0, %1}, %2;" : "=f"(lo1), "=f"(hi1) : "l"(acc[j][1]));
        const int t = tok0 + tg + 32 * j;
        float4 o4;
        o4.x = lo0 + bv.x;
        o4.y = hi0 + bv.y;
        o4.z = lo1 + bv.z;
        o4.w = hi1 + bv.w;
        *(float4*)(out + (size_t)t * OUT_F + rb * BH + colq * 4) = o4;
    }
}

extern "C" void kernel_launch(void* const* d_in, const int* in_sizes, int n_in,
                              void* d_out, int out_size) {
    (void)in_sizes; (void)n_in; (void)out_size;
    const float* x    = (const float*)d_in[0];
    const float* w    = (const float*)d_in[1];
    const float* bias = (const float*)d_in[2];
    const int*   brow = (const int*)d_in[3];
    const int*   bcol = (const int*)d_in[4];
    float* out = (float*)d_out;

    spmm_prep_kernel<<<1, N_RB>>>(brow, bcol);
    dim3 grid(N_TOKENS / TOK_TILE, N_RB);
    spmm_main_kernel<<<grid, THREADS>>>(x, w, bias, out);
}

// round 4
// speedup vs baseline: 1.2941x; 1.2941x over previous
#include <cuda_runtime.h>
#include <cstdint>
#include <cstddef>

#define N_TOKENS   16384
#define IN_F       1024
#define OUT_F      1024
#define BH         32
#define BW         32
#define NB         256
#define N_RB       (OUT_F / BH)   // 32
#define TOK_TILE   256
#define THREADS    256

__device__ int g_cnt[N_RB];
__device__ int g_blk[N_RB][NB];
__device__ int g_col[N_RB][NB];

__global__ void spmm_prep_kernel(const int* __restrict__ brow,
                                 const int* __restrict__ bcol) {
    int rb = threadIdx.x;
    if (rb >= N_RB) return;
    int c = 0;
    for (int b = 0; b < NB; ++b) {
        if (brow[b] == rb) { g_blk[rb][c] = b; g_col[rb][c] = bcol[b]; ++c; }
    }
    g_cnt[rb] = c;
}

__device__ __forceinline__ unsigned tf32_hi(float v) {
    return __float_as_uint(v) & 0xffffe000u;   // exactly 10 explicit mantissa bits
}

__device__ __forceinline__ void mma_tf32(float* d, const unsigned* a, const unsigned* b) {
    asm volatile(
        "mma.sync.aligned.m16n8k8.row.col.f32.tf32.tf32.f32 "
        "{%0,%1,%2,%3}, {%4,%5,%6,%7}, {%8,%9}, {%0,%1,%2,%3};"
        : "+f"(d[0]), "+f"(d[1]), "+f"(d[2]), "+f"(d[3])
        : "r"(a[0]), "r"(a[1]), "r"(a[2]), "r"(a[3]), "r"(b[0]), "r"(b[1]));
}

// CTA: 256 tokens x one 32-wide output row-block. 8 warps, each fully
// independent: 32 tokens x 32 outs, accumulated in mma.sync tf32 fragments.
// k within each k8 step is interleaved (fragment col c -> 2c, c+4 -> 2c+1,
// same permutation for A and B) so all fragment loads are contiguous LDG.64.
__global__ __launch_bounds__(THREADS)
void spmm_main_kernel(const float* __restrict__ x,
                      const float* __restrict__ w,
                      const float* __restrict__ bias,
                      float* __restrict__ out) {
    const int rb   = blockIdx.y;
    const int tok0 = blockIdx.x * TOK_TILE;
    const int wid  = threadIdx.x >> 5;
    const int lane = threadIdx.x & 31;
    const int g    = lane >> 2;   // 0..7
    const int c    = lane & 3;    // 0..3

    float acc[2][4][4];
#pragma unroll
    for (int mt = 0; mt < 2; ++mt)
#pragma unroll
        for (int nt = 0; nt < 4; ++nt)
#pragma unroll
            for (int r = 0; r < 4; ++r) acc[mt][nt][r] = 0.0f;

    const int cnt = g_cnt[rb];
    const float* xw = x + (size_t)(tok0 + wid * 32) * IN_F;

    for (int i = 0; i < cnt; ++i) {
        const int b  = g_blk[rb][i];
        const int cb = g_col[rb][i];
        const float* xb = xw + cb * BW;
        const float* wb = w + (size_t)b * (BH * BW);

#pragma unroll
        for (int s = 0; s < 4; ++s) {
            const int kc = s * 8 + 2 * c;   // interleaved k pair base

            // ---- A fragments (x), hi/lo split ----
            unsigned ahi[2][4], alo[2][4];
#pragma unroll
            for (int mt = 0; mt < 2; ++mt) {
                const float2 A0 = *(const float2*)(xb + (size_t)(mt * 16 + g)     * IN_F + kc);
                const float2 A1 = *(const float2*)(xb + (size_t)(mt * 16 + g + 8) * IN_F + kc);
                // a0: (row g,  col c)   a1: (row g+8, col c)
                // a2: (row g,  col c+4) a3: (row g+8, col c+4)
                ahi[mt][0] = tf32_hi(A0.x);
                ahi[mt][1] = tf32_hi(A1.x);
                ahi[mt][2] = tf32_hi(A0.y);
                ahi[mt][3] = tf32_hi(A1.y);
                alo[mt][0] = __float_as_uint(A0.x - __uint_as_float(ahi[mt][0]));
                alo[mt][1] = __float_as_uint(A1.x - __uint_as_float(ahi[mt][1]));
                alo[mt][2] = __float_as_uint(A0.y - __uint_as_float(ahi[mt][2]));
                alo[mt][3] = __float_as_uint(A1.y - __uint_as_float(ahi[mt][3]));
            }

            // ---- B fragments (w), hi/lo split, then 3-term MMAs ----
#pragma unroll
            for (int nt = 0; nt < 4; ++nt) {
                const float2 B = *(const float2*)(wb + (nt * 8 + g) * BW + kc);
                unsigned bhi[2], blo[2];
                bhi[0] = tf32_hi(B.x);
                bhi[1] = tf32_hi(B.y);
                blo[0] = __float_as_uint(B.x - __uint_as_float(bhi[0]));
                blo[1] = __float_as_uint(B.y - __uint_as_float(bhi[1]));
#pragma unroll
                for (int mt = 0; mt < 2; ++mt) {
                    mma_tf32(acc[mt][nt], ahi[mt], bhi);
                    mma_tf32(acc[mt][nt], ahi[mt], blo);
                    mma_tf32(acc[mt][nt], alo[mt], bhi);
                }
            }
        }
    }

    // ---- epilogue: add bias, store (STG.64, coalesced within 8-row groups) ----
    const float* bp = bias + rb * BH;
#pragma unroll
    for (int nt = 0; nt < 4; ++nt) {
        const float2 bv = *(const float2*)(bp + nt * 8 + 2 * c);
#pragma unroll
        for (int mt = 0; mt < 2; ++mt) {
            const int row0 = tok0 + wid * 32 + mt * 16 + g;
            float2 o0, o1;
            o0.x = acc[mt][nt][0] + bv.x;
            o0.y = acc[mt][nt][1] + bv.y;
            o1.x = acc[mt][nt][2] + bv.x;
            o1.y = acc[mt][nt][3] + bv.y;
            *(float2*)(out + (size_t)row0       * OUT_F + rb * BH + nt * 8 + 2 * c) = o0;
            *(float2*)(out + (size_t)(row0 + 8) * OUT_F + rb * BH + nt * 8 + 2 * c) = o1;
        }
    }
}

extern "C" void kernel_launch(void* const* d_in, const int* in_sizes, int n_in,
                              void* d_out, int out_size) {
    (void)in_sizes; (void)n_in; (void)out_size;
    const float* x    = (const float*)d_in[0];
    const float* w    = (const float*)d_in[1];
    const float* bias = (const float*)d_in[2];
    const int*   brow = (const int*)d_in[3];
    const int*   bcol = (const int*)d_in[4];
    float* out = (float*)d_out;

    spmm_prep_kernel<<<1, N_RB>>>(brow, bcol);
    dim3 grid(N_TOKENS / TOK_TILE, N_RB);
    spmm_main_kernel<<<grid, THREADS>>>(x, w, bias, out);
}